// round 7
// baseline (speedup 1.0000x reference)
#include <cuda_runtime.h>
#include <cuda_bf16.h>
#include <cuda_fp16.h>
#include <cstdint>

// Problem constants
#define B_   4
#define L_   256
#define E_   256
#define K3_  768
#define NL_  6

// ---------------- scratch ----------------
__device__ __align__(16) __half g_wh[589824];            // weights fp16 [kind][t][f][e]
__device__ __align__(16) __half g_eh[B_ * 260 * 256];    // gathered emb fp16, rows = l+1 (0 & 257..259 zero)
__device__ __align__(16) __nv_bfloat16 g_B[(size_t)B_ * L_ * K3_];  // conv feat bf16

#define W2OFF 0
#define W3OFF 131072
#define W4OFF 327680

// ---------------------------------------------------------------------------
// Kernel 1: prep — weight transpose+cvt to fp16, embedding gather to fp16.
// ---------------------------------------------------------------------------
__global__ __launch_bounds__(256) void prep_kernel(
    const int* __restrict__ ids, const float* __restrict__ emb,
    const float* __restrict__ w2, const float* __restrict__ w3,
    const float* __restrict__ w4)
{
    const int bx = blockIdx.x, tid = threadIdx.x;
    if (bx < 2304) {
        int idx = bx * 256 + tid;              // [kind][t][f][e] flat
        const float* w; int off, taps;
        if (idx < 327680) {
            if (idx < 131072) { w = w2; off = W2OFF; taps = 2; }
            else              { w = w3; off = W3OFF; taps = 3; }
        } else                { w = w4; off = W4OFF; taps = 4; }
        int widx = idx - off;
        int t = widx >> 16;
        int f = (widx >> 8) & 255;
        int e = widx & 255;
        g_wh[idx] = __float2half_rn(w[(f * 256 + e) * taps + t]);
    } else {
        int bx2 = bx - 2304;                   // 0..1039 = b*260 + row
        int b = bx2 / 260, row = bx2 - b * 260;
        int l = row - 1;
        __half v = __float2half_rn(0.0f);
        if (l >= 0 && l < L_) {
            int id = ids[b * L_ + l];
            v = __float2half_rn(emb[(size_t)id * E_ + tid]);
        }
        g_eh[(size_t)(b * 260 + row) * 256 + tid] = v;
    }
}

// ---------------------------------------------------------------------------
// Shared mma helpers
// ---------------------------------------------------------------------------
__device__ __forceinline__ void ldsm_x4(uint32_t* r, uint32_t addr) {
    asm volatile("ldmatrix.sync.aligned.m8n8.x4.shared.b16 {%0,%1,%2,%3}, [%4];"
        : "=r"(r[0]), "=r"(r[1]), "=r"(r[2]), "=r"(r[3]) : "r"(addr));
}
__device__ __forceinline__ void mma_h(float* c, const uint32_t* a, const uint32_t* b) {
    asm volatile("mma.sync.aligned.m16n8k16.row.col.f32.f16.f16.f32 "
        "{%0,%1,%2,%3}, {%4,%5,%6,%7}, {%8,%9}, {%0,%1,%2,%3};"
        : "+f"(c[0]), "+f"(c[1]), "+f"(c[2]), "+f"(c[3])
        : "r"(a[0]), "r"(a[1]), "r"(a[2]), "r"(a[3]), "r"(b[0]), "r"(b[1]));
}
__device__ __forceinline__ void mma_bf(float* c, const uint32_t* a, const uint32_t* b) {
    asm volatile("mma.sync.aligned.m16n8k16.row.col.f32.bf16.bf16.f32 "
        "{%0,%1,%2,%3}, {%4,%5,%6,%7}, {%8,%9}, {%0,%1,%2,%3};"
        : "+f"(c[0]), "+f"(c[1]), "+f"(c[2]), "+f"(c[3])
        : "r"(a[0]), "r"(a[1]), "r"(a[2]), "r"(a[3]), "r"(b[0]), "r"(b[1]));
}
__device__ __forceinline__ uint32_t mulpack(float2 v, float2 w) {
    __nv_bfloat162 r = __floats2bfloat162_rn(v.x * w.x, v.y * w.y);
    return *reinterpret_cast<uint32_t*>(&r);
}

// ---------------------------------------------------------------------------
// Kernel 2: conv via fp16 mma. CTA: 64l x 32f of one (b, kind, ftile).
// Whole E=256 staged in smem at once (one sync). Taps = shifted ldmatrix rows
// into the halo'd embedding tile. 8 warps = 4(L) x 2(F).
// ---------------------------------------------------------------------------
#define ESTR 264
#define CONV_SMEM ((68 + 128) * ESTR * 2)   // 103,488 B

template<int TAPS, int SHIFT>
__device__ __forceinline__ void conv_mainloop(
    uint32_t eB, uint32_t wB, int warpL, int warpF, int lane, float acc[2][4])
{
    const int arow  = warpL * 16 + (lane & 15) + SHIFT;
    const int ahalf = (lane >> 4) * 8;
    const int brow  = warpF * 16 + (lane >> 4) * 8 + (lane & 7);
    const int bhalf = ((lane >> 3) & 1) * 8;
    #pragma unroll
    for (int t = 0; t < TAPS; t++) {
        #pragma unroll
        for (int ks = 0; ks < 16; ks++) {
            uint32_t a[4], r4[4];
            ldsm_x4(a,  eB + ((arow + t) * ESTR + ks * 16 + ahalf) * 2);
            ldsm_x4(r4, wB + ((t * 32 + brow) * ESTR + ks * 16 + bhalf) * 2);
            mma_h(acc[0], a, r4);
            mma_h(acc[1], a, r4 + 2);
        }
    }
}

__global__ __launch_bounds__(256) void conv_f16_kernel(
    const float* __restrict__ b2, const float* __restrict__ b3,
    const float* __restrict__ b4)
{
    extern __shared__ __align__(16) __half csm[];
    __half* sE = csm;                 // [68][ESTR]
    __half* sW = csm + 68 * ESTR;     // [taps*32][ESTR]
    __shared__ float sBias[32];

    const int tid  = threadIdx.x;
    const int lane = tid & 31;
    const int wid  = tid >> 5;
    const int warpL = wid >> 1;
    const int warpF = wid & 1;

    const int l0   = blockIdx.x * 64;
    const int kind = blockIdx.y >> 3;
    const int ft   = blockIdx.y & 7;
    const int b    = blockIdx.z;
    const int taps = kind + 2;
    const int fbase = (kind == 0) ? 0 : (kind == 1) ? 256 : 512;
    const int woff  = (kind == 0) ? W2OFF : (kind == 1) ? W3OFF : W4OFF;
    const int kg0   = fbase + ft * 32;

    if (tid < 32) {
        const float* bias = (kind == 0) ? b2 : (kind == 1) ? b3 : b4;
        sBias[tid] = bias[ft * 32 + tid];
    }

    // Stage A (68 halo'd emb rows) and W (taps*32 filter rows), full E.
    const __half* gE = g_eh + ((size_t)(b * 260 + l0)) * 256;
    for (int idx = tid; idx < 68 * 32; idx += 256) {
        int row = idx >> 5, q = idx & 31;
        uint32_t dst = (uint32_t)__cvta_generic_to_shared(sE + row * ESTR + q * 8);
        const void* src = gE + (size_t)row * 256 + q * 8;
        asm volatile("cp.async.cg.shared.global [%0], [%1], 16;" :: "r"(dst), "l"(src));
    }
    for (int idx = tid; idx < taps * 1024; idx += 256) {
        int row = idx >> 5, q = idx & 31;     // row = t*32 + f
        int t = row >> 5, f = row & 31;
        uint32_t dst = (uint32_t)__cvta_generic_to_shared(sW + row * ESTR + q * 8);
        const void* src = g_wh + woff + ((size_t)(t * 256 + ft * 32 + f)) * 256 + q * 8;
        asm volatile("cp.async.cg.shared.global [%0], [%1], 16;" :: "r"(dst), "l"(src));
    }
    asm volatile("cp.async.commit_group;");
    asm volatile("cp.async.wait_group 0;");
    __syncthreads();

    float acc[2][4] = {};
    uint32_t eB = (uint32_t)__cvta_generic_to_shared(sE);
    uint32_t wB = (uint32_t)__cvta_generic_to_shared(sW);
    if (taps == 2)      conv_mainloop<2, 1>(eB, wB, warpL, warpF, lane, acc);
    else if (taps == 3) conv_mainloop<3, 0>(eB, wB, warpL, warpF, lane, acc);
    else                conv_mainloop<4, 0>(eB, wB, warpL, warpF, lane, acc);

    // --- epilogue: stage C in smem, dense bf16 store of g_B ---
    __syncthreads();
    float* Cs = reinterpret_cast<float*>(csm);   // [64][40]
    #pragma unroll
    for (int nf = 0; nf < 2; nf++) {
        const int col = warpF * 16 + nf * 8 + (lane & 3) * 2;
        #pragma unroll
        for (int half = 0; half < 2; half++) {
            const int row = warpL * 16 + (lane >> 2) + half * 8;
            *reinterpret_cast<float2*>(&Cs[row * 40 + col]) =
                make_float2(acc[nf][half * 2 + 0], acc[nf][half * 2 + 1]);
        }
    }
    __syncthreads();

    const int row = tid >> 2;
    const int c8  = (tid & 3) * 8;
    float f[8];
    *reinterpret_cast<float4*>(f)     = *reinterpret_cast<float4*>(&Cs[row * 40 + c8]);
    *reinterpret_cast<float4*>(f + 4) = *reinterpret_cast<float4*>(&Cs[row * 40 + c8 + 4]);
    __nv_bfloat162 p[4];
    #pragma unroll
    for (int q = 0; q < 4; q++)
        p[q] = __floats2bfloat162_rn(f[2 * q] + sBias[c8 + 2 * q],
                                     f[2 * q + 1] + sBias[c8 + 2 * q + 1]);
    *reinterpret_cast<uint4*>(
        &g_B[((size_t)(b * L_ + l0 + row)) * K3_ + kg0 + c8]) =
        *reinterpret_cast<uint4*>(p);
}

// ---------------------------------------------------------------------------
// Kernel 3: pair GEMM, A-fragments (feat_i * w_h) built on the fly.
// CTA: 128m (16 i x 8 h, h=7 zero) x 64n. K=768 in 12 chunks of 64,
// 4-stage cp.async. 8 warps = 4(M:32) x 2(N:32). Grid 16 x 4 x 4 = 256.
// ---------------------------------------------------------------------------
#define SMSB 72                       // bf16 k-stride (64 + 8 pad)
#define WT_OFF 0                      // float2[384*8] = 24,576 B
#define FI_OFF 24576                  // 4 x 16*72*2 = 9,216 B
#define FI_STG 2304
#define BS_OFF 33792                  // 4 x 64*72*2 = 36,864 B
#define BS_STG 9216
#define PAIR_SMEM 70656

__global__ __launch_bounds__(256) void pair_mma_kernel(
    const float* __restrict__ tw, const float* __restrict__ tb,
    const float* __restrict__ sw, const float* __restrict__ sb,
    float* __restrict__ out)
{
    extern __shared__ __align__(16) char psm[];
    float2* wT = reinterpret_cast<float2*>(psm + WT_OFF);   // [384 kp][8 h]
    const uint32_t su = (uint32_t)__cvta_generic_to_shared(psm);

    const int tid  = threadIdx.x;
    const int lane = tid & 31;
    const int wid  = tid >> 5;
    const int wm   = (wid >> 1) * 32;   // 0,32,64,96
    const int wn   = (wid & 1) * 32;    // 0,32

    const int b  = blockIdx.z;
    const int i0 = blockIdx.x * 16;
    const int n0 = blockIdx.y * 64;

    for (int idx = tid; idx < 3072; idx += 256) {
        int kp = idx >> 3, h = idx & 7;
        float w0 = 0.0f, w1 = 0.0f;
        if (h < 6)       { w0 = tw[h * K3_ + 2 * kp]; w1 = tw[h * K3_ + 2 * kp + 1]; }
        else if (h == 6) { w0 = sw[2 * kp];           w1 = sw[2 * kp + 1]; }
        wT[idx] = make_float2(w0, w1);
    }

    const __nv_bfloat16* gI = g_B + ((size_t)(b * L_ + i0)) * K3_;
    const __nv_bfloat16* gJ = g_B + ((size_t)(b * L_ + n0)) * K3_;

    auto load_stage = [&](int stage, int k0) {
        #pragma unroll
        for (int r = 0; r < 2; r++) {
            int idx = tid + r * 256;
            int row = idx >> 3, q = idx & 7;
            uint32_t dst = su + BS_OFF + stage * BS_STG + (row * SMSB + q * 8) * 2;
            const void* src = gJ + (size_t)row * K3_ + k0 + q * 8;
            asm volatile("cp.async.cg.shared.global [%0], [%1], 16;" :: "r"(dst), "l"(src));
        }
        if (tid < 128) {
            int row = tid >> 3, q = tid & 7;
            uint32_t dst = su + FI_OFF + stage * FI_STG + (row * SMSB + q * 8) * 2;
            const void* src = gI + (size_t)row * K3_ + k0 + q * 8;
            asm volatile("cp.async.cg.shared.global [%0], [%1], 16;" :: "r"(dst), "l"(src));
        }
        asm volatile("cp.async.commit_group;");
    };

    float acc[2][4][4] = {};

    load_stage(0, 0);
    load_stage(1, 64);
    load_stage(2, 128);
    __syncthreads();   // wT + stage visibility

    float bb[6];
    #pragma unroll
    for (int h = 0; h < 6; h++) bb[h] = tb[h];
    const float sb0 = sb[0];

    const int q    = lane & 3;
    const int h    = lane >> 2;
    const int p    = lane >> 4;
    const int half = (lane >> 3) & 1;
    const int ib0  = wm >> 3;
    const int browb = wn + p * 8 + (lane & 7);

    for (int it = 0; it < 12; it++) {
        if (it < 10)       asm volatile("cp.async.wait_group 2;");
        else if (it == 10) asm volatile("cp.async.wait_group 1;");
        else               asm volatile("cp.async.wait_group 0;");
        __syncthreads();

        if (it + 3 < 12) load_stage((it + 3) & 3, (it + 3) * 64);

        const int st = it & 3;
        const __nv_bfloat162* fI = reinterpret_cast<const __nv_bfloat162*>(
            psm + FI_OFF + st * FI_STG);
        const uint32_t bBase = su + BS_OFF + st * BS_STG;
        const int kp0 = it * 32;

        #pragma unroll
        for (int ksg = 0; ksg < 4; ksg++) {
            const int ks  = ksg * 16;
            const int kq  = ksg * 8 + q;
            const int kpg = kp0 + kq;
            const float2 wlo = wT[kpg * 8 + h];
            const float2 whi = wT[(kpg + 4) * 8 + h];

            uint32_t a[2][4];
            #pragma unroll
            for (int fm = 0; fm < 2; fm++) {
                const int ib = ib0 + fm * 2;
                float2 v00 = __bfloat1622float2(fI[ib * 36 + kq]);
                float2 v10 = __bfloat1622float2(fI[(ib + 1) * 36 + kq]);
                float2 v01 = __bfloat1622float2(fI[ib * 36 + kq + 4]);
                float2 v11 = __bfloat1622float2(fI[(ib + 1) * 36 + kq + 4]);
                a[fm][0] = mulpack(v00, wlo);
                a[fm][1] = mulpack(v10, wlo);
                a[fm][2] = mulpack(v01, whi);
                a[fm][3] = mulpack(v11, whi);
            }

            uint32_t bf[4][2];
            #pragma unroll
            for (int fp = 0; fp < 2; fp++) {
                uint32_t r4[4];
                ldsm_x4(r4, bBase + ((browb + fp * 16) * SMSB + ks + half * 8) * 2);
                bf[fp * 2][0]     = r4[0]; bf[fp * 2][1]     = r4[1];
                bf[fp * 2 + 1][0] = r4[2]; bf[fp * 2 + 1][1] = r4[3];
            }

            #pragma unroll
            for (int fm = 0; fm < 2; fm++)
                #pragma unroll
                for (int fn = 0; fn < 4; fn++)
                    mma_bf(acc[fm][fn], a[fm], bf[fn]);
        }
    }

    // --- epilogue: stage C tile [128][68] in smem, dense output ---
    __syncthreads();
    float* Cs = reinterpret_cast<float*>(psm);
    #pragma unroll
    for (int fm = 0; fm < 2; fm++) {
        const int r0 = wm + fm * 16 + (lane >> 2);
        #pragma unroll
        for (int fn = 0; fn < 4; fn++) {
            const int c0 = wn + fn * 8 + (lane & 3) * 2;
            *reinterpret_cast<float2*>(&Cs[r0 * 68 + c0]) =
                make_float2(acc[fm][fn][0], acc[fm][fn][1]);
            *reinterpret_cast<float2*>(&Cs[(r0 + 8) * 68 + c0]) =
                make_float2(acc[fm][fn][2], acc[fm][fn][3]);
        }
    }
    __syncthreads();

    // triple logits: 16 il x 64 j x 6 h = 1536 float4, 6 per thread
    #pragma unroll
    for (int r = 0; r < 6; r++) {
        const int fidx = tid + r * 256;
        const int il = fidx / 96;
        const int o  = (fidx - il * 96) * 4;
        float4 v;
        { int o0 = o;     int j = o0 / 6, hh = o0 - j * 6; v.x = Cs[(il * 8 + hh) * 68 + j] + bb[hh]; }
        { int o1 = o + 1; int j = o1 / 6, hh = o1 - j * 6; v.y = Cs[(il * 8 + hh) * 68 + j] + bb[hh]; }
        { int o2 = o + 2; int j = o2 / 6, hh = o2 - j * 6; v.z = Cs[(il * 8 + hh) * 68 + j] + bb[hh]; }
        { int o3 = o + 3; int j = o3 / 6, hh = o3 - j * 6; v.w = Cs[(il * 8 + hh) * 68 + j] + bb[hh]; }
        *reinterpret_cast<float4*>(
            out + ((size_t)((b * L_ + i0 + il) * L_ + n0)) * NL_ + o) = v;
    }

    // scores: 16 il x 64 j = 256 float4, 1 per thread
    {
        float* sc = out + (size_t)B_ * L_ * L_ * NL_;
        const int il = tid >> 4;
        const int j4 = (tid & 15) * 4;
        float4 v;
        v.x = Cs[(il * 8 + 6) * 68 + j4 + 0] + sb0;
        v.y = Cs[(il * 8 + 6) * 68 + j4 + 1] + sb0;
        v.z = Cs[(il * 8 + 6) * 68 + j4 + 2] + sb0;
        v.w = Cs[(il * 8 + 6) * 68 + j4 + 3] + sb0;
        *reinterpret_cast<float4*>(
            sc + (size_t)(b * L_ + i0 + il) * L_ + n0 + j4) = v;
    }
}

// ---------------------------------------------------------------------------
extern "C" void kernel_launch(void* const* d_in, const int* in_sizes, int n_in,
                              void* d_out, int out_size) {
    const int*   ids = (const int*)  d_in[0];
    const float* emb = (const float*)d_in[1];
    const float* w2  = (const float*)d_in[2];
    const float* b2  = (const float*)d_in[3];
    const float* w3  = (const float*)d_in[4];
    const float* b3  = (const float*)d_in[5];
    const float* w4  = (const float*)d_in[6];
    const float* b4  = (const float*)d_in[7];
    const float* tw  = (const float*)d_in[8];
    const float* tb  = (const float*)d_in[9];
    const float* sw  = (const float*)d_in[10];
    const float* sb  = (const float*)d_in[11];
    float* out = (float*)d_out;

    cudaFuncSetAttribute(conv_f16_kernel,
        cudaFuncAttributeMaxDynamicSharedMemorySize, CONV_SMEM);
    cudaFuncSetAttribute(pair_mma_kernel,
        cudaFuncAttributeMaxDynamicSharedMemorySize, PAIR_SMEM);

    prep_kernel<<<2304 + B_ * 260, 256>>>(ids, emb, w2, w3, w4);

    dim3 cgrid(4, 24, 4);    // 384 CTAs
    conv_f16_kernel<<<cgrid, 256, CONV_SMEM>>>(b2, b3, b4);

    dim3 pgrid(16, 4, 4);    // 256 CTAs
    pair_mma_kernel<<<pgrid, 256, PAIR_SMEM>>>(tw, tb, sw, sb, out);
}

// round 8
// speedup vs baseline: 1.6361x; 1.6361x over previous
#include <cuda_runtime.h>
#include <cuda_bf16.h>
#include <cuda_fp16.h>
#include <cstdint>

// Problem constants
#define B_   4
#define L_   256
#define E_   256
#define K3_  768
#define NL_  6

// ---------------- scratch ----------------
__device__ __align__(16) __half g_wh[589824];            // weights fp16 [kind][t][f][e]
__device__ __align__(16) __half g_eh[B_ * 260 * 256];    // gathered emb fp16, row = l+1
__device__ __align__(16) __nv_bfloat16 g_B[(size_t)B_ * L_ * K3_];  // conv feat bf16

#define W2OFF 0
#define W3OFF 131072
#define W4OFF 327680

// ---------------------------------------------------------------------------
// Kernel 1: prep. Blocks 0..95: weight transpose [f][e][t] -> [kind][t][f][e]
// (8 f-rows per block, smem staged, coalesced both sides). Blocks 96+: emb
// gather to fp16 (one l-row per block).
// ---------------------------------------------------------------------------
__global__ __launch_bounds__(256) void prep_kernel(
    const int* __restrict__ ids, const float* __restrict__ emb,
    const float* __restrict__ w2, const float* __restrict__ w3,
    const float* __restrict__ w4)
{
    __shared__ float sbuf[8 * 1024];      // 8 f x 256e x up-to-4t
    const int bx = blockIdx.x, tid = threadIdx.x;

    if (bx < 96) {
        const int kind = bx >> 5;                 // 0..2
        const int f0   = (bx & 31) * 8;
        const int taps = kind + 2;
        const float* __restrict__ w =
            (kind == 0) ? w2 : (kind == 1) ? w3 : w4;
        const int woff = (kind == 0) ? W2OFF : (kind == 1) ? W3OFF : W4OFF;
        const int rowlen = 256 * taps;

        for (int idx = tid; idx < 8 * rowlen; idx += 256) {
            int f = idx / rowlen;
            int within = idx - f * rowlen;
            sbuf[f * rowlen + within] = w[(size_t)(f0 + f) * rowlen + within];
        }
        __syncthreads();

        uint32_t* outw = reinterpret_cast<uint32_t*>(g_wh + woff);
        const int m = taps * 8 * 128;
        for (int idx = tid; idx < m; idx += 256) {
            int ep = idx & 127;
            int f  = (idx >> 7) & 7;
            int t  = idx >> 10;
            float lo = sbuf[f * rowlen + (2 * ep) * taps + t];
            float hi = sbuf[f * rowlen + (2 * ep + 1) * taps + t];
            __half2 h2 = __floats2half2_rn(lo, hi);
            outw[(t * 256 + f0 + f) * 128 + ep] = *reinterpret_cast<uint32_t*>(&h2);
        }
    } else {
        const int bx2 = bx - 96;                  // b*260 + row
        const int b = bx2 / 260, row = bx2 - b * 260;
        const int l = row - 1;
        __half v = __float2half_rn(0.0f);
        if (l >= 0 && l < L_) {
            int id = ids[b * L_ + l];
            v = __float2half_rn(emb[(size_t)id * E_ + tid]);
        }
        g_eh[(size_t)(b * 260 + row) * 256 + tid] = v;
    }
}

// ---------------------------------------------------------------------------
// mma helpers
// ---------------------------------------------------------------------------
__device__ __forceinline__ void ldsm_x4(uint32_t* r, uint32_t addr) {
    asm volatile("ldmatrix.sync.aligned.m8n8.x4.shared.b16 {%0,%1,%2,%3}, [%4];"
        : "=r"(r[0]), "=r"(r[1]), "=r"(r[2]), "=r"(r[3]) : "r"(addr));
}
__device__ __forceinline__ void mma_h(float* c, const uint32_t* a, const uint32_t* b) {
    asm volatile("mma.sync.aligned.m16n8k16.row.col.f32.f16.f16.f32 "
        "{%0,%1,%2,%3}, {%4,%5,%6,%7}, {%8,%9}, {%0,%1,%2,%3};"
        : "+f"(c[0]), "+f"(c[1]), "+f"(c[2]), "+f"(c[3])
        : "r"(a[0]), "r"(a[1]), "r"(a[2]), "r"(a[3]), "r"(b[0]), "r"(b[1]));
}
__device__ __forceinline__ void mma_bf(float* c, const uint32_t* a, const uint32_t* b) {
    asm volatile("mma.sync.aligned.m16n8k16.row.col.f32.bf16.bf16.f32 "
        "{%0,%1,%2,%3}, {%4,%5,%6,%7}, {%8,%9}, {%0,%1,%2,%3};"
        : "+f"(c[0]), "+f"(c[1]), "+f"(c[2]), "+f"(c[3])
        : "r"(a[0]), "r"(a[1]), "r"(a[2]), "r"(a[3]), "r"(b[0]), "r"(b[1]));
}
__device__ __forceinline__ uint32_t mul_bf16x2(uint32_t a, uint32_t b) {
    uint32_t r;
    asm("mul.bf16x2 %0, %1, %2;" : "=r"(r) : "r"(a), "r"(b));
    return r;
}

// ---------------------------------------------------------------------------
// Kernel 2: conv via fp16 mma. CTA: 64l x 32f of one (b, kind, ftile).
// E in 4 chunks of 64, 3-stage cp.async. 8 warps = 4(L) x 2(F).
// ---------------------------------------------------------------------------
#define ESTR 72
#define CA_STG (68 * ESTR)
#define CW_STG (128 * ESTR)
#define CONV_SMEM (3 * (CA_STG + CW_STG) * 2)   // 84,672 B

template<int TAPS, int SHIFT>
__device__ __forceinline__ void conv_chunk(
    uint32_t eB, uint32_t wB, int warpL, int warpF, int lane, float acc[2][4])
{
    const int arow  = warpL * 16 + (lane & 15) + SHIFT;
    const int ahalf = (lane >> 4) * 8;
    const int brow  = warpF * 16 + (lane >> 4) * 8 + (lane & 7);
    const int bhalf = ((lane >> 3) & 1) * 8;
    #pragma unroll
    for (int t = 0; t < TAPS; t++) {
        #pragma unroll
        for (int ks = 0; ks < 4; ks++) {
            uint32_t a[4], r4[4];
            ldsm_x4(a,  eB + ((arow + t) * ESTR + ks * 16 + ahalf) * 2);
            ldsm_x4(r4, wB + ((t * 32 + brow) * ESTR + ks * 16 + bhalf) * 2);
            mma_h(acc[0], a, r4);
            mma_h(acc[1], a, r4 + 2);
        }
    }
}

__global__ __launch_bounds__(256) void conv_f16_kernel(
    const float* __restrict__ b2, const float* __restrict__ b3,
    const float* __restrict__ b4)
{
    extern __shared__ __align__(16) __half csm[];
    __half* sE = csm;                     // 3 x [68][72]
    __half* sW = csm + 3 * CA_STG;        // 3 x [128][72]
    __shared__ float sBias[32];

    const int tid  = threadIdx.x;
    const int lane = tid & 31;
    const int wid  = tid >> 5;
    const int warpL = wid >> 1;
    const int warpF = wid & 1;

    const int l0   = blockIdx.x * 64;
    const int kind = blockIdx.y >> 3;
    const int ft   = blockIdx.y & 7;
    const int b    = blockIdx.z;
    const int taps = kind + 2;
    const int fbase = (kind == 0) ? 0 : (kind == 1) ? 256 : 512;
    const int woff  = (kind == 0) ? W2OFF : (kind == 1) ? W3OFF : W4OFF;
    const int kg0   = fbase + ft * 32;

    if (tid < 32) {
        const float* bias = (kind == 0) ? b2 : (kind == 1) ? b3 : b4;
        sBias[tid] = bias[ft * 32 + tid];
    }

    const __half* gE = g_eh + ((size_t)(b * 260 + l0)) * 256;

    auto load_chunk = [&](int c) {
        const int stg = c % 3;
        const int e0  = c * 64;
        __half* dA = sE + stg * CA_STG;
        for (int idx = tid; idx < 68 * 8; idx += 256) {
            int row = idx >> 3, q = idx & 7;
            uint32_t dst = (uint32_t)__cvta_generic_to_shared(dA + row * ESTR + q * 8);
            const void* src = gE + (size_t)row * 256 + e0 + q * 8;
            asm volatile("cp.async.cg.shared.global [%0], [%1], 16;" :: "r"(dst), "l"(src));
        }
        __half* dW = sW + stg * CW_STG;
        for (int idx = tid; idx < taps * 32 * 8; idx += 256) {
            int row = idx >> 3, q = idx & 7;   // row = t*32 + f
            int t = row >> 5, f = row & 31;
            uint32_t dst = (uint32_t)__cvta_generic_to_shared(dW + row * ESTR + q * 8);
            const void* src = g_wh + woff + ((size_t)(t * 256 + ft * 32 + f)) * 256 + e0 + q * 8;
            asm volatile("cp.async.cg.shared.global [%0], [%1], 16;" :: "r"(dst), "l"(src));
        }
        asm volatile("cp.async.commit_group;");
    };

    float acc[2][4] = {};

    load_chunk(0);
    load_chunk(1);

    for (int c = 0; c < 4; c++) {
        if (c < 3) asm volatile("cp.async.wait_group 1;");
        else       asm volatile("cp.async.wait_group 0;");
        __syncthreads();
        if (c + 2 < 4) load_chunk(c + 2);

        uint32_t eB = (uint32_t)__cvta_generic_to_shared(sE + (c % 3) * CA_STG);
        uint32_t wB = (uint32_t)__cvta_generic_to_shared(sW + (c % 3) * CW_STG);
        if (taps == 2)      conv_chunk<2, 1>(eB, wB, warpL, warpF, lane, acc);
        else if (taps == 3) conv_chunk<3, 0>(eB, wB, warpL, warpF, lane, acc);
        else                conv_chunk<4, 0>(eB, wB, warpL, warpF, lane, acc);
        __syncthreads();
    }

    // --- epilogue: stage C in smem, dense bf16 store of g_B ---
    float* Cs = reinterpret_cast<float*>(csm);   // [64][40]
    #pragma unroll
    for (int nf = 0; nf < 2; nf++) {
        const int col = warpF * 16 + nf * 8 + (lane & 3) * 2;
        #pragma unroll
        for (int half = 0; half < 2; half++) {
            const int row = warpL * 16 + (lane >> 2) + half * 8;
            *reinterpret_cast<float2*>(&Cs[row * 40 + col]) =
                make_float2(acc[nf][half * 2 + 0], acc[nf][half * 2 + 1]);
        }
    }
    __syncthreads();

    const int row = tid >> 2;
    const int c8  = (tid & 3) * 8;
    float f[8];
    *reinterpret_cast<float4*>(f)     = *reinterpret_cast<float4*>(&Cs[row * 40 + c8]);
    *reinterpret_cast<float4*>(f + 4) = *reinterpret_cast<float4*>(&Cs[row * 40 + c8 + 4]);
    __nv_bfloat162 p[4];
    #pragma unroll
    for (int q = 0; q < 4; q++)
        p[q] = __floats2bfloat162_rn(f[2 * q] + sBias[c8 + 2 * q],
                                     f[2 * q + 1] + sBias[c8 + 2 * q + 1]);
    *reinterpret_cast<uint4*>(
        &g_B[((size_t)(b * L_ + l0 + row)) * K3_ + kg0 + c8]) =
        *reinterpret_cast<uint4*>(p);
}

// ---------------------------------------------------------------------------
// Kernel 3: pair GEMM, A-frags = bf16x2(feat_i) * bf16x2(w_h) via mul.bf16x2.
// CTA: 128m (16 i x 8 h, h=7 zero) x 128n. K=768: 12 chunks of 64, 3-stage.
// 8 warps = 4(M:32) x 2(N:64). Double-buffered fragments. Grid 16 x 2 x 4.
// ---------------------------------------------------------------------------
#define SMSB 72
#define WT_OFF 0                      // uint32[384*8] = 12,288 B
#define FI_OFF 12288                  // 3 x 16*72*2 = 6,912 B
#define FI_STG 2304
#define BS_OFF 19200                  // 3 x 128*72*2 = 55,296 B
#define BS_STG 18432
#define PAIR_SMEM 74496               // epilogue Cs 128*132*4 = 67,584 fits

__global__ __launch_bounds__(256) void pair_mma_kernel(
    const float* __restrict__ tw, const float* __restrict__ tb,
    const float* __restrict__ sw, const float* __restrict__ sb,
    float* __restrict__ out)
{
    extern __shared__ __align__(16) char psm[];
    uint32_t* wTs = reinterpret_cast<uint32_t*>(psm + WT_OFF);   // [384 kp][8 h]
    const uint32_t su = (uint32_t)__cvta_generic_to_shared(psm);

    const int tid  = threadIdx.x;
    const int lane = tid & 31;
    const int wid  = tid >> 5;
    const int wm   = (wid >> 1) * 32;   // 0,32,64,96
    const int wn   = (wid & 1) * 64;    // 0,64

    const int b  = blockIdx.z;
    const int i0 = blockIdx.x * 16;
    const int n0 = blockIdx.y * 128;

    // wT: bf16x2 of (w[2kp], w[2kp+1]) per head
    for (int idx = tid; idx < 3072; idx += 256) {
        int kp = idx >> 3, h = idx & 7;
        float w0 = 0.0f, w1 = 0.0f;
        if (h < 6)       { w0 = tw[h * K3_ + 2 * kp]; w1 = tw[h * K3_ + 2 * kp + 1]; }
        else if (h == 6) { w0 = sw[2 * kp];           w1 = sw[2 * kp + 1]; }
        __nv_bfloat162 p = __floats2bfloat162_rn(w0, w1);
        wTs[idx] = *reinterpret_cast<uint32_t*>(&p);
    }

    const __nv_bfloat16* gI = g_B + ((size_t)(b * L_ + i0)) * K3_;
    const __nv_bfloat16* gJ = g_B + ((size_t)(b * L_ + n0)) * K3_;

    auto load_stage = [&](int stage, int k0) {
        #pragma unroll
        for (int r = 0; r < 4; r++) {
            int idx = tid + r * 256;
            int row = idx >> 3, q = idx & 7;
            uint32_t dst = su + BS_OFF + stage * BS_STG + (row * SMSB + q * 8) * 2;
            const void* src = gJ + (size_t)row * K3_ + k0 + q * 8;
            asm volatile("cp.async.cg.shared.global [%0], [%1], 16;" :: "r"(dst), "l"(src));
        }
        if (tid < 128) {
            int row = tid >> 3, q = tid & 7;
            uint32_t dst = su + FI_OFF + stage * FI_STG + (row * SMSB + q * 8) * 2;
            const void* src = gI + (size_t)row * K3_ + k0 + q * 8;
            asm volatile("cp.async.cg.shared.global [%0], [%1], 16;" :: "r"(dst), "l"(src));
        }
        asm volatile("cp.async.commit_group;");
    };

    float acc[2][8][4] = {};

    load_stage(0, 0);
    load_stage(1, 64);

    const int q    = lane & 3;
    const int h    = lane >> 2;
    const int p    = lane >> 4;
    const int half = (lane >> 3) & 1;
    const int ib0  = wm >> 3;
    const int browb = wn + p * 8 + (lane & 7);

    uint32_t a[2][2][4];     // [buf][fm][4]
    uint32_t bf[2][8][2];    // [buf][fn][2]

    for (int it = 0; it < 12; it++) {
        if (it < 11) asm volatile("cp.async.wait_group 1;");
        else         asm volatile("cp.async.wait_group 0;");
        __syncthreads();

        if (it + 2 < 12) load_stage((it + 2) % 3, (it + 2) * 64);

        const int st = it % 3;
        const uint32_t* fIu = reinterpret_cast<const uint32_t*>(psm + FI_OFF + st * FI_STG);
        const uint32_t bBase = su + BS_OFF + st * BS_STG;
        const int kp0 = it * 32;

        auto frag_load = [&](int ksg, int buf) {
            const int kq  = ksg * 8 + q;
            const int kpg = kp0 + kq;
            const uint32_t wlo = wTs[kpg * 8 + h];
            const uint32_t whi = wTs[(kpg + 4) * 8 + h];
            #pragma unroll
            for (int fm = 0; fm < 2; fm++) {
                const int ib = ib0 + 2 * fm;
                a[buf][fm][0] = mul_bf16x2(fIu[ib * 36 + kq], wlo);
                a[buf][fm][1] = mul_bf16x2(fIu[(ib + 1) * 36 + kq], wlo);
                a[buf][fm][2] = mul_bf16x2(fIu[ib * 36 + kq + 4], whi);
                a[buf][fm][3] = mul_bf16x2(fIu[(ib + 1) * 36 + kq + 4], whi);
            }
            const int ks = ksg * 16;
            #pragma unroll
            for (int fp = 0; fp < 4; fp++) {
                uint32_t r4[4];
                ldsm_x4(r4, bBase + ((browb + fp * 16) * SMSB + ks + half * 8) * 2);
                bf[buf][fp * 2][0]     = r4[0]; bf[buf][fp * 2][1]     = r4[1];
                bf[buf][fp * 2 + 1][0] = r4[2]; bf[buf][fp * 2 + 1][1] = r4[3];
            }
        };

        frag_load(0, 0);
        #pragma unroll
        for (int ksg = 0; ksg < 4; ksg++) {
            const int cur = ksg & 1;
            if (ksg < 3) frag_load(ksg + 1, cur ^ 1);
            #pragma unroll
            for (int fm = 0; fm < 2; fm++)
                #pragma unroll
                for (int fn = 0; fn < 8; fn++)
                    mma_bf(acc[fm][fn], a[cur][fm], bf[cur][fn]);
        }
    }

    float bb[6];
    #pragma unroll
    for (int hh = 0; hh < 6; hh++) bb[hh] = tb[hh];
    const float sb0 = sb[0];

    // --- epilogue: stage C tile [128][132] in smem, dense output ---
    __syncthreads();
    float* Cs = reinterpret_cast<float*>(psm);
    #pragma unroll
    for (int fm = 0; fm < 2; fm++) {
        const int r0 = wm + fm * 16 + (lane >> 2);
        #pragma unroll
        for (int fn = 0; fn < 8; fn++) {
            const int c0 = wn + fn * 8 + (lane & 3) * 2;
            *reinterpret_cast<float2*>(&Cs[r0 * 132 + c0]) =
                make_float2(acc[fm][fn][0], acc[fm][fn][1]);
            *reinterpret_cast<float2*>(&Cs[(r0 + 8) * 132 + c0]) =
                make_float2(acc[fm][fn][2], acc[fm][fn][3]);
        }
    }
    __syncthreads();

    // triple logits: 16 il x 128 j x 6 h = 3072 float4, 12 per thread
    #pragma unroll
    for (int r = 0; r < 12; r++) {
        const int fidx = tid + r * 256;
        const int il = fidx / 192;
        const int o  = (fidx - il * 192) * 4;
        float4 v;
        { int o0 = o;     int j = o0 / 6, hh = o0 - j * 6; v.x = Cs[(il * 8 + hh) * 132 + j] + bb[hh]; }
        { int o1 = o + 1; int j = o1 / 6, hh = o1 - j * 6; v.y = Cs[(il * 8 + hh) * 132 + j] + bb[hh]; }
        { int o2 = o + 2; int j = o2 / 6, hh = o2 - j * 6; v.z = Cs[(il * 8 + hh) * 132 + j] + bb[hh]; }
        { int o3 = o + 3; int j = o3 / 6, hh = o3 - j * 6; v.w = Cs[(il * 8 + hh) * 132 + j] + bb[hh]; }
        *reinterpret_cast<float4*>(
            out + ((size_t)((b * L_ + i0 + il) * L_ + n0)) * NL_ + o) = v;
    }

    // scores: 16 il x 128 j = 512 float4, 2 per thread
    {
        float* sc = out + (size_t)B_ * L_ * L_ * NL_;
        #pragma unroll
        for (int r = 0; r < 2; r++) {
            const int fidx = tid + r * 256;
            const int il = fidx >> 5;
            const int j4 = (fidx & 31) * 4;
            float4 v;
            v.x = Cs[(il * 8 + 6) * 132 + j4 + 0] + sb0;
            v.y = Cs[(il * 8 + 6) * 132 + j4 + 1] + sb0;
            v.z = Cs[(il * 8 + 6) * 132 + j4 + 2] + sb0;
            v.w = Cs[(il * 8 + 6) * 132 + j4 + 3] + sb0;
            *reinterpret_cast<float4*>(
                sc + (size_t)(b * L_ + i0 + il) * L_ + n0 + j4) = v;
        }
    }
}

// ---------------------------------------------------------------------------
extern "C" void kernel_launch(void* const* d_in, const int* in_sizes, int n_in,
                              void* d_out, int out_size) {
    const int*   ids = (const int*)  d_in[0];
    const float* emb = (const float*)d_in[1];
    const float* w2  = (const float*)d_in[2];
    const float* b2  = (const float*)d_in[3];
    const float* w3  = (const float*)d_in[4];
    const float* b3  = (const float*)d_in[5];
    const float* w4  = (const float*)d_in[6];
    const float* b4  = (const float*)d_in[7];
    const float* tw  = (const float*)d_in[8];
    const float* tb  = (const float*)d_in[9];
    const float* sw  = (const float*)d_in[10];
    const float* sb  = (const float*)d_in[11];
    float* out = (float*)d_out;

    cudaFuncSetAttribute(conv_f16_kernel,
        cudaFuncAttributeMaxDynamicSharedMemorySize, CONV_SMEM);
    cudaFuncSetAttribute(pair_mma_kernel,
        cudaFuncAttributeMaxDynamicSharedMemorySize, PAIR_SMEM);

    prep_kernel<<<96 + B_ * 260, 256>>>(ids, emb, w2, w3, w4);

    dim3 cgrid(4, 24, 4);    // 384 CTAs
    conv_f16_kernel<<<cgrid, 256, CONV_SMEM>>>(b2, b3, b4);

    dim3 pgrid(16, 2, 4);    // 128 CTAs
    pair_mma_kernel<<<pgrid, 256, PAIR_SMEM>>>(tw, tb, sw, sb, out);
}

// round 9
// speedup vs baseline: 1.8500x; 1.1308x over previous
#include <cuda_runtime.h>
#include <cuda_bf16.h>
#include <cuda_fp16.h>
#include <cstdint>

// Problem constants
#define B_   4
#define L_   256
#define E_   256
#define K3_  768
#define NL_  6

// ---------------- scratch ----------------
__device__ __align__(16) __half g_wh[589824];            // weights fp16 [kind][t][f][e]
__device__ __align__(16) __half g_eh[B_ * 260 * 256];    // gathered emb fp16, row = l+1
__device__ __align__(16) uint32_t g_wt[384 * 8];         // pair w table bf16x2 [kp][h]
__device__ __align__(16) __nv_bfloat16 g_B[(size_t)B_ * L_ * K3_];  // conv feat bf16

#define W2OFF 0
#define W3OFF 131072
#define W4OFF 327680

// ---------------------------------------------------------------------------
// Kernel 1: prep.
//   blocks 0..95    : weight transpose [f][e][t] -> [kind][t][f][e] fp16
//   blocks 96..128  : emb gather to fp16 (32 rows per block, warp per row)
//   block  129      : pair w table (bf16x2 [384 kp][8 h])
// ---------------------------------------------------------------------------
__global__ __launch_bounds__(256) void prep_kernel(
    const int* __restrict__ ids, const float* __restrict__ emb,
    const float* __restrict__ w2, const float* __restrict__ w3,
    const float* __restrict__ w4,
    const float* __restrict__ tw, const float* __restrict__ sw)
{
    __shared__ float sbuf[8 * 1024];
    const int bx = blockIdx.x, tid = threadIdx.x;

    if (bx < 96) {
        const int kind = bx >> 5;
        const int f0   = (bx & 31) * 8;
        const int taps = kind + 2;
        const float* __restrict__ w =
            (kind == 0) ? w2 : (kind == 1) ? w3 : w4;
        const int woff = (kind == 0) ? W2OFF : (kind == 1) ? W3OFF : W4OFF;
        const int rowlen = 256 * taps;

        for (int idx = tid; idx < 8 * rowlen; idx += 256) {
            int f = idx / rowlen;
            int within = idx - f * rowlen;
            sbuf[f * rowlen + within] = w[(size_t)(f0 + f) * rowlen + within];
        }
        __syncthreads();

        uint32_t* outw = reinterpret_cast<uint32_t*>(g_wh + woff);
        const int m = taps * 8 * 128;
        for (int idx = tid; idx < m; idx += 256) {
            int ep = idx & 127;
            int f  = (idx >> 7) & 7;
            int t  = idx >> 10;
            float lo = sbuf[f * rowlen + (2 * ep) * taps + t];
            float hi = sbuf[f * rowlen + (2 * ep + 1) * taps + t];
            __half2 h2 = __floats2half2_rn(lo, hi);
            outw[(t * 256 + f0 + f) * 128 + ep] = *reinterpret_cast<uint32_t*>(&h2);
        }
    } else if (bx < 129) {
        // emb gather: 32 rows per block, one warp per row (4 sweeps of 8 rows)
        const int base = (bx - 96) * 32;
        const int lane = tid & 31;
        #pragma unroll
        for (int s = 0; s < 4; s++) {
            const int row = base + s * 8 + (tid >> 5);
            if (row >= B_ * 260) continue;
            const int b = row / 260;
            const int rr = row - b * 260;
            const int l = rr - 1;
            __half2 h[4];
            if (l >= 0 && l < L_) {
                const int id = ids[b * L_ + l];
                const float4* src = reinterpret_cast<const float4*>(
                    emb + (size_t)id * E_ + lane * 8);
                float4 v0 = src[0], v1 = src[1];
                h[0] = __floats2half2_rn(v0.x, v0.y);
                h[1] = __floats2half2_rn(v0.z, v0.w);
                h[2] = __floats2half2_rn(v1.x, v1.y);
                h[3] = __floats2half2_rn(v1.z, v1.w);
            } else {
                h[0] = h[1] = h[2] = h[3] = __floats2half2_rn(0.f, 0.f);
            }
            *reinterpret_cast<uint4*>(g_eh + (size_t)row * 256 + lane * 8) =
                *reinterpret_cast<uint4*>(h);
        }
    } else {
        // pair w table
        for (int idx = tid; idx < 3072; idx += 256) {
            int kp = idx >> 3, h = idx & 7;
            float w0 = 0.0f, w1 = 0.0f;
            if (h < 6)       { w0 = tw[h * K3_ + 2 * kp]; w1 = tw[h * K3_ + 2 * kp + 1]; }
            else if (h == 6) { w0 = sw[2 * kp];           w1 = sw[2 * kp + 1]; }
            __nv_bfloat162 p = __floats2bfloat162_rn(w0, w1);
            g_wt[idx] = *reinterpret_cast<uint32_t*>(&p);
        }
    }
}

// ---------------------------------------------------------------------------
// mma helpers
// ---------------------------------------------------------------------------
__device__ __forceinline__ void ldsm_x4(uint32_t* r, uint32_t addr) {
    asm volatile("ldmatrix.sync.aligned.m8n8.x4.shared.b16 {%0,%1,%2,%3}, [%4];"
        : "=r"(r[0]), "=r"(r[1]), "=r"(r[2]), "=r"(r[3]) : "r"(addr));
}
__device__ __forceinline__ void mma_h(float* c, const uint32_t* a, const uint32_t* b) {
    asm volatile("mma.sync.aligned.m16n8k16.row.col.f32.f16.f16.f32 "
        "{%0,%1,%2,%3}, {%4,%5,%6,%7}, {%8,%9}, {%0,%1,%2,%3};"
        : "+f"(c[0]), "+f"(c[1]), "+f"(c[2]), "+f"(c[3])
        : "r"(a[0]), "r"(a[1]), "r"(a[2]), "r"(a[3]), "r"(b[0]), "r"(b[1]));
}
__device__ __forceinline__ void mma_bf(float* c, const uint32_t* a, const uint32_t* b) {
    asm volatile("mma.sync.aligned.m16n8k16.row.col.f32.bf16.bf16.f32 "
        "{%0,%1,%2,%3}, {%4,%5,%6,%7}, {%8,%9}, {%0,%1,%2,%3};"
        : "+f"(c[0]), "+f"(c[1]), "+f"(c[2]), "+f"(c[3])
        : "r"(a[0]), "r"(a[1]), "r"(a[2]), "r"(a[3]), "r"(b[0]), "r"(b[1]));
}
__device__ __forceinline__ uint32_t mul_bf16x2(uint32_t a, uint32_t b) {
    uint32_t r;
    asm("mul.bf16x2 %0, %1, %2;" : "=r"(r) : "r"(a), "r"(b));
    return r;
}

// ---------------------------------------------------------------------------
// Kernel 2: conv via fp16 mma. CTA: 64l x 32f of one (b, kind, ftile).
// E in 4 chunks of 64, 3-stage cp.async. 8 warps = 4(L) x 2(F).
// ---------------------------------------------------------------------------
#define ESTR 72
#define CA_STG (68 * ESTR)
#define CW_STG (128 * ESTR)
#define CONV_SMEM (3 * (CA_STG + CW_STG) * 2)   // 84,672 B

template<int TAPS, int SHIFT>
__device__ __forceinline__ void conv_chunk(
    uint32_t eB, uint32_t wB, int warpL, int warpF, int lane, float acc[2][4])
{
    const int arow  = warpL * 16 + (lane & 15) + SHIFT;
    const int ahalf = (lane >> 4) * 8;
    const int brow  = warpF * 16 + (lane >> 4) * 8 + (lane & 7);
    const int bhalf = ((lane >> 3) & 1) * 8;
    #pragma unroll
    for (int t = 0; t < TAPS; t++) {
        #pragma unroll
        for (int ks = 0; ks < 4; ks++) {
            uint32_t a[4], r4[4];
            ldsm_x4(a,  eB + ((arow + t) * ESTR + ks * 16 + ahalf) * 2);
            ldsm_x4(r4, wB + ((t * 32 + brow) * ESTR + ks * 16 + bhalf) * 2);
            mma_h(acc[0], a, r4);
            mma_h(acc[1], a, r4 + 2);
        }
    }
}

__global__ __launch_bounds__(256) void conv_f16_kernel(
    const float* __restrict__ b2, const float* __restrict__ b3,
    const float* __restrict__ b4)
{
    extern __shared__ __align__(16) __half csm[];
    __half* sE = csm;                     // 3 x [68][72]
    __half* sW = csm + 3 * CA_STG;        // 3 x [128][72]
    __shared__ float sBias[32];

    const int tid  = threadIdx.x;
    const int lane = tid & 31;
    const int wid  = tid >> 5;
    const int warpL = wid >> 1;
    const int warpF = wid & 1;

    const int l0   = blockIdx.x * 64;
    const int kind = blockIdx.y >> 3;
    const int ft   = blockIdx.y & 7;
    const int b    = blockIdx.z;
    const int taps = kind + 2;
    const int fbase = (kind == 0) ? 0 : (kind == 1) ? 256 : 512;
    const int woff  = (kind == 0) ? W2OFF : (kind == 1) ? W3OFF : W4OFF;
    const int kg0   = fbase + ft * 32;

    if (tid < 32) {
        const float* bias = (kind == 0) ? b2 : (kind == 1) ? b3 : b4;
        sBias[tid] = bias[ft * 32 + tid];
    }

    const __half* gE = g_eh + ((size_t)(b * 260 + l0)) * 256;

    auto load_chunk = [&](int c) {
        const int stg = c % 3;
        const int e0  = c * 64;
        __half* dA = sE + stg * CA_STG;
        for (int idx = tid; idx < 68 * 8; idx += 256) {
            int row = idx >> 3, q = idx & 7;
            uint32_t dst = (uint32_t)__cvta_generic_to_shared(dA + row * ESTR + q * 8);
            const void* src = gE + (size_t)row * 256 + e0 + q * 8;
            asm volatile("cp.async.cg.shared.global [%0], [%1], 16;" :: "r"(dst), "l"(src));
        }
        __half* dW = sW + stg * CW_STG;
        for (int idx = tid; idx < taps * 32 * 8; idx += 256) {
            int row = idx >> 3, q = idx & 7;   // row = t*32 + f
            int t = row >> 5, f = row & 31;
            uint32_t dst = (uint32_t)__cvta_generic_to_shared(dW + row * ESTR + q * 8);
            const void* src = g_wh + woff + ((size_t)(t * 256 + ft * 32 + f)) * 256 + e0 + q * 8;
            asm volatile("cp.async.cg.shared.global [%0], [%1], 16;" :: "r"(dst), "l"(src));
        }
        asm volatile("cp.async.commit_group;");
    };

    float acc[2][4] = {};

    load_chunk(0);
    load_chunk(1);

    for (int c = 0; c < 4; c++) {
        if (c < 3) asm volatile("cp.async.wait_group 1;");
        else       asm volatile("cp.async.wait_group 0;");
        __syncthreads();
        if (c + 2 < 4) load_chunk(c + 2);

        uint32_t eB = (uint32_t)__cvta_generic_to_shared(sE + (c % 3) * CA_STG);
        uint32_t wB = (uint32_t)__cvta_generic_to_shared(sW + (c % 3) * CW_STG);
        if (taps == 2)      conv_chunk<2, 1>(eB, wB, warpL, warpF, lane, acc);
        else if (taps == 3) conv_chunk<3, 0>(eB, wB, warpL, warpF, lane, acc);
        else                conv_chunk<4, 0>(eB, wB, warpL, warpF, lane, acc);
        __syncthreads();
    }

    // --- epilogue: stage C in smem, dense bf16 store of g_B ---
    float* Cs = reinterpret_cast<float*>(csm);   // [64][40]
    #pragma unroll
    for (int nf = 0; nf < 2; nf++) {
        const int col = warpF * 16 + nf * 8 + (lane & 3) * 2;
        #pragma unroll
        for (int half = 0; half < 2; half++) {
            const int row = warpL * 16 + (lane >> 2) + half * 8;
            *reinterpret_cast<float2*>(&Cs[row * 40 + col]) =
                make_float2(acc[nf][half * 2 + 0], acc[nf][half * 2 + 1]);
        }
    }
    __syncthreads();

    const int row = tid >> 2;
    const int c8  = (tid & 3) * 8;
    float f[8];
    *reinterpret_cast<float4*>(f)     = *reinterpret_cast<float4*>(&Cs[row * 40 + c8]);
    *reinterpret_cast<float4*>(f + 4) = *reinterpret_cast<float4*>(&Cs[row * 40 + c8 + 4]);
    __nv_bfloat162 p[4];
    #pragma unroll
    for (int q = 0; q < 4; q++)
        p[q] = __floats2bfloat162_rn(f[2 * q] + sBias[c8 + 2 * q],
                                     f[2 * q + 1] + sBias[c8 + 2 * q + 1]);
    *reinterpret_cast<uint4*>(
        &g_B[((size_t)(b * L_ + l0 + row)) * K3_ + kg0 + c8]) =
        *reinterpret_cast<uint4*>(p);
}

// ---------------------------------------------------------------------------
// Kernel 3: pair GEMM, A-frags = bf16x2(feat_i) * bf16x2(w_h) via mul.bf16x2.
// CTA: 128m (16 i x 8 h, h=7 zero) x 128n. K=768: 12 chunks of 64, 3-stage.
// 8 warps = 4(M:32) x 2(N:64). Double-buffered fragments. Grid 16 x 2 x 4.
// ---------------------------------------------------------------------------
#define SMSB 72
#define WT_OFF 0                      // uint32[384*8] = 12,288 B
#define FI_OFF 12288                  // 3 x 16*72*2 = 6,912 B
#define FI_STG 2304
#define BS_OFF 19200                  // 3 x 128*72*2 = 55,296 B
#define BS_STG 18432
#define PAIR_SMEM 74496               // epilogue Cs 128*132*4 = 67,584 fits

__global__ __launch_bounds__(256) void pair_mma_kernel(
    const float* __restrict__ tb, const float* __restrict__ sb,
    float* __restrict__ out)
{
    extern __shared__ __align__(16) char psm[];
    uint32_t* wTs = reinterpret_cast<uint32_t*>(psm + WT_OFF);   // [384 kp][8 h]
    const uint32_t su = (uint32_t)__cvta_generic_to_shared(psm);

    const int tid  = threadIdx.x;
    const int lane = tid & 31;
    const int wid  = tid >> 5;
    const int wm   = (wid >> 1) * 32;   // 0,32,64,96
    const int wn   = (wid & 1) * 64;    // 0,64

    const int b  = blockIdx.z;
    const int i0 = blockIdx.x * 16;
    const int n0 = blockIdx.y * 128;

    const __nv_bfloat16* gI = g_B + ((size_t)(b * L_ + i0)) * K3_;
    const __nv_bfloat16* gJ = g_B + ((size_t)(b * L_ + n0)) * K3_;

    // wT table via cp.async (folded into stage-0 commit group)
    #pragma unroll
    for (int r = 0; r < 3; r++) {
        int q = tid + r * 256;              // 768 x 16B
        uint32_t dst = su + WT_OFF + q * 16;
        const void* src = reinterpret_cast<const char*>(g_wt) + q * 16;
        asm volatile("cp.async.cg.shared.global [%0], [%1], 16;" :: "r"(dst), "l"(src));
    }

    auto load_stage = [&](int stage, int k0) {
        #pragma unroll
        for (int r = 0; r < 4; r++) {
            int idx = tid + r * 256;
            int row = idx >> 3, q = idx & 7;
            uint32_t dst = su + BS_OFF + stage * BS_STG + (row * SMSB + q * 8) * 2;
            const void* src = gJ + (size_t)row * K3_ + k0 + q * 8;
            asm volatile("cp.async.cg.shared.global [%0], [%1], 16;" :: "r"(dst), "l"(src));
        }
        if (tid < 128) {
            int row = tid >> 3, q = tid & 7;
            uint32_t dst = su + FI_OFF + stage * FI_STG + (row * SMSB + q * 8) * 2;
            const void* src = gI + (size_t)row * K3_ + k0 + q * 8;
            asm volatile("cp.async.cg.shared.global [%0], [%1], 16;" :: "r"(dst), "l"(src));
        }
        asm volatile("cp.async.commit_group;");
    };

    float acc[2][8][4] = {};

    load_stage(0, 0);
    load_stage(1, 64);

    const int q    = lane & 3;
    const int h    = lane >> 2;
    const int p    = lane >> 4;
    const int half = (lane >> 3) & 1;
    const int ib0  = wm >> 3;
    const int browb = wn + p * 8 + (lane & 7);

    uint32_t a[2][2][4];     // [buf][fm][4]
    uint32_t bf[2][8][2];    // [buf][fn][2]

    for (int it = 0; it < 12; it++) {
        if (it < 11) asm volatile("cp.async.wait_group 1;");
        else         asm volatile("cp.async.wait_group 0;");
        __syncthreads();

        if (it + 2 < 12) load_stage((it + 2) % 3, (it + 2) * 64);

        const int st = it % 3;
        const uint32_t* fIu = reinterpret_cast<const uint32_t*>(psm + FI_OFF + st * FI_STG);
        const uint32_t bBase = su + BS_OFF + st * BS_STG;
        const int kp0 = it * 32;

        auto frag_load = [&](int ksg, int buf) {
            const int kq  = ksg * 8 + q;
            const int kpg = kp0 + kq;
            const uint32_t wlo = wTs[kpg * 8 + h];
            const uint32_t whi = wTs[(kpg + 4) * 8 + h];
            #pragma unroll
            for (int fm = 0; fm < 2; fm++) {
                const int ib = ib0 + 2 * fm;
                a[buf][fm][0] = mul_bf16x2(fIu[ib * 36 + kq], wlo);
                a[buf][fm][1] = mul_bf16x2(fIu[(ib + 1) * 36 + kq], wlo);
                a[buf][fm][2] = mul_bf16x2(fIu[ib * 36 + kq + 4], whi);
                a[buf][fm][3] = mul_bf16x2(fIu[(ib + 1) * 36 + kq + 4], whi);
            }
            const int ks = ksg * 16;
            #pragma unroll
            for (int fp = 0; fp < 4; fp++) {
                uint32_t r4[4];
                ldsm_x4(r4, bBase + ((browb + fp * 16) * SMSB + ks + half * 8) * 2);
                bf[buf][fp * 2][0]     = r4[0]; bf[buf][fp * 2][1]     = r4[1];
                bf[buf][fp * 2 + 1][0] = r4[2]; bf[buf][fp * 2 + 1][1] = r4[3];
            }
        };

        frag_load(0, 0);
        #pragma unroll
        for (int ksg = 0; ksg < 4; ksg++) {
            const int cur = ksg & 1;
            if (ksg < 3) frag_load(ksg + 1, cur ^ 1);
            #pragma unroll
            for (int fm = 0; fm < 2; fm++)
                #pragma unroll
                for (int fn = 0; fn < 8; fn++)
                    mma_bf(acc[fm][fn], a[cur][fm], bf[cur][fn]);
        }
    }

    float bb[6];
    #pragma unroll
    for (int hh = 0; hh < 6; hh++) bb[hh] = tb[hh];
    const float sb0 = sb[0];

    // --- epilogue: stage C tile [128][132] in smem, dense output ---
    __syncthreads();
    float* Cs = reinterpret_cast<float*>(psm);
    #pragma unroll
    for (int fm = 0; fm < 2; fm++) {
        const int r0 = wm + fm * 16 + (lane >> 2);
        #pragma unroll
        for (int fn = 0; fn < 8; fn++) {
            const int c0 = wn + fn * 8 + (lane & 3) * 2;
            *reinterpret_cast<float2*>(&Cs[r0 * 132 + c0]) =
                make_float2(acc[fm][fn][0], acc[fm][fn][1]);
            *reinterpret_cast<float2*>(&Cs[(r0 + 8) * 132 + c0]) =
                make_float2(acc[fm][fn][2], acc[fm][fn][3]);
        }
    }
    __syncthreads();

    // triple logits: 16 il x 128 j x 6 h = 3072 float4, 12 per thread
    #pragma unroll
    for (int r = 0; r < 12; r++) {
        const int fidx = tid + r * 256;
        const int il = fidx / 192;
        const int o  = (fidx - il * 192) * 4;
        float4 v;
        { int o0 = o;     int j = o0 / 6, hh = o0 - j * 6; v.x = Cs[(il * 8 + hh) * 132 + j] + bb[hh]; }
        { int o1 = o + 1; int j = o1 / 6, hh = o1 - j * 6; v.y = Cs[(il * 8 + hh) * 132 + j] + bb[hh]; }
        { int o2 = o + 2; int j = o2 / 6, hh = o2 - j * 6; v.z = Cs[(il * 8 + hh) * 132 + j] + bb[hh]; }
        { int o3 = o + 3; int j = o3 / 6, hh = o3 - j * 6; v.w = Cs[(il * 8 + hh) * 132 + j] + bb[hh]; }
        *reinterpret_cast<float4*>(
            out + ((size_t)((b * L_ + i0 + il) * L_ + n0)) * NL_ + o) = v;
    }

    // scores: 16 il x 128 j = 512 float4, 2 per thread
    {
        float* sc = out + (size_t)B_ * L_ * L_ * NL_;
        #pragma unroll
        for (int r = 0; r < 2; r++) {
            const int fidx = tid + r * 256;
            const int il = fidx >> 5;
            const int j4 = (fidx & 31) * 4;
            float4 v;
            v.x = Cs[(il * 8 + 6) * 132 + j4 + 0] + sb0;
            v.y = Cs[(il * 8 + 6) * 132 + j4 + 1] + sb0;
            v.z = Cs[(il * 8 + 6) * 132 + j4 + 2] + sb0;
            v.w = Cs[(il * 8 + 6) * 132 + j4 + 3] + sb0;
            *reinterpret_cast<float4*>(
                sc + (size_t)(b * L_ + i0 + il) * L_ + n0 + j4) = v;
        }
    }
}

// ---------------------------------------------------------------------------
extern "C" void kernel_launch(void* const* d_in, const int* in_sizes, int n_in,
                              void* d_out, int out_size) {
    const int*   ids = (const int*)  d_in[0];
    const float* emb = (const float*)d_in[1];
    const float* w2  = (const float*)d_in[2];
    const float* b2  = (const float*)d_in[3];
    const float* w3  = (const float*)d_in[4];
    const float* b3  = (const float*)d_in[5];
    const float* w4  = (const float*)d_in[6];
    const float* b4  = (const float*)d_in[7];
    const float* tw  = (const float*)d_in[8];
    const float* tb  = (const float*)d_in[9];
    const float* sw  = (const float*)d_in[10];
    const float* sb  = (const float*)d_in[11];
    float* out = (float*)d_out;

    cudaFuncSetAttribute(conv_f16_kernel,
        cudaFuncAttributeMaxDynamicSharedMemorySize, CONV_SMEM);
    cudaFuncSetAttribute(pair_mma_kernel,
        cudaFuncAttributeMaxDynamicSharedMemorySize, PAIR_SMEM);

    prep_kernel<<<130, 256>>>(ids, emb, w2, w3, w4, tw, sw);

    dim3 cgrid(4, 24, 4);    // 384 CTAs
    conv_f16_kernel<<<cgrid, 256, CONV_SMEM>>>(b2, b3, b4);

    dim3 pgrid(16, 2, 4);    // 128 CTAs
    pair_mma_kernel<<<pgrid, 256, PAIR_SMEM>>>(tb, sb, out);
}